// round 8
// baseline (speedup 1.0000x reference)
#include <cuda_runtime.h>
#include <cuda_bf16.h>
#include <math.h>
#include <stdint.h>

#define BT_N 64
#define LQ   256
#define LK   512
#define CDIM 512
#define NH   8
#define HD   64

typedef __nv_bfloat16 bf16;

// ---- device scratch ----
__device__ bf16 g_qbf [(size_t)16384 * 512];
__device__ bf16 g_kvbf[(size_t)32768 * 512];
__device__ bf16 g_wq  [512 * 512];
__device__ bf16 g_wkv [1024 * 512];
__device__ bf16 g_wm  [512 * 512];
__device__ bf16 g_qh  [(size_t)BT_N * NH * LQ * HD];
__device__ bf16 g_kh  [(size_t)BT_N * NH * LK * HD];
__device__ bf16 g_vt  [(size_t)BT_N * NH * HD * LK];   // V transposed: [bt][h][d][lk]
__device__ bf16 g_xm  [(size_t)BT_N * LQ * CDIM];

// ---------------------------------------------------------------------------
__device__ __forceinline__ unsigned pk(float lo, float hi) {
    unsigned r;
    asm("cvt.rn.bf16x2.f32 %0, %1, %2;" : "=r"(r) : "f"(hi), "f"(lo));
    return r;
}
__device__ __forceinline__ uint32_t smem_u32(const void* p) {
    uint32_t a;
    asm("{ .reg .u64 t; cvta.to.shared.u64 t, %1; cvt.u32.u64 %0, t; }" : "=r"(a) : "l"(p));
    return a;
}
__device__ __forceinline__ void cp_async16(uint32_t dst, const void* src) {
    asm volatile("cp.async.cg.shared.global [%0], [%1], 16;" :: "r"(dst), "l"(src));
}
__device__ __forceinline__ void cp_commit() { asm volatile("cp.async.commit_group;" ::: "memory"); }
template<int N> __device__ __forceinline__ void cp_wait() { asm volatile("cp.async.wait_group %0;" :: "n"(N) : "memory"); }

__device__ __forceinline__ void ldm_x4(unsigned* r, uint32_t addr) {
    asm volatile("ldmatrix.sync.aligned.m8n8.x4.shared.b16 {%0,%1,%2,%3}, [%4];"
                 : "=r"(r[0]), "=r"(r[1]), "=r"(r[2]), "=r"(r[3]) : "r"(addr));
}

__device__ __forceinline__ void mma16816(float* d, const unsigned* a, unsigned b0, unsigned b1) {
    asm volatile(
        "mma.sync.aligned.m16n8k16.row.col.f32.bf16.bf16.f32 "
        "{%0,%1,%2,%3},{%4,%5,%6,%7},{%8,%9},{%0,%1,%2,%3};"
        : "+f"(d[0]), "+f"(d[1]), "+f"(d[2]), "+f"(d[3])
        : "r"(a[0]), "r"(a[1]), "r"(a[2]), "r"(a[3]), "r"(b0), "r"(b1));
}

// ---------------------------------------------------------------------------
// fp32 -> bf16 conversions (merged)
// ---------------------------------------------------------------------------
#define Q8   (16384 * 512 / 8)
#define KV8  (32768 * 512 / 8)
#define WQ8  (512 * 512 / 8)
#define WKV8 (1024 * 512 / 8)
#define WM8  (512 * 512 / 8)

__device__ __forceinline__ void conv8(const float* src, bf16* dst, int i) {
    const float4 a = ((const float4*)src)[2 * i];
    const float4 b = ((const float4*)src)[2 * i + 1];
    ((uint4*)dst)[i] = make_uint4(pk(a.x, a.y), pk(a.z, a.w), pk(b.x, b.y), pk(b.z, b.w));
}

__global__ __launch_bounds__(256) void convert_inputs(const float* __restrict__ q,
                                                      const float* __restrict__ kv) {
    int i = blockIdx.x * blockDim.x + threadIdx.x;
    if (i < Q8) conv8(q, g_qbf, i);
    else        conv8(kv, g_kvbf, i - Q8);
}
__global__ __launch_bounds__(256) void convert_weights(const float* __restrict__ wq,
                                                       const float* __restrict__ wkv,
                                                       const float* __restrict__ wm) {
    int i = blockIdx.x * blockDim.x + threadIdx.x;
    if (i < WQ8)             conv8(wq, g_wq, i);
    else if (i < WQ8 + WKV8) conv8(wkv, g_wkv, i - WQ8);
    else                     conv8(wm, g_wm, i - WQ8 - WKV8);
}

// ---------------------------------------------------------------------------
// bf16 GEMM (NT): CTA 128x128, 128 threads (4 warps 2Mx2N), warp tile 64x64.
// BK=64, 3-stage cp.async, ldmatrix. Row stride 72 bf16 = 144 B.
// Stage = 36864 B; 3 stages = 110592 B -> 2 CTA/SM.
// ---------------------------------------------------------------------------
#define GSTAGE 36864
#define GSMEM  (3 * GSTAGE)

template<int MODE>
__global__ __launch_bounds__(128, 2)
void gemm_bf16(const float* __restrict__ bias,
               const float* __restrict__ shortcut,
               float* __restrict__ out)
{
    extern __shared__ bf16 dsm[];
    const uint32_t smBase = smem_u32(dsm);

    const int tid   = threadIdx.x;
    const int lane  = tid & 31;
    const int wid   = tid >> 5;        // 0..3
    const int warpM = wid >> 1;        // 0..1
    const int warpN = wid & 1;         // 0..1
    const int g     = lane >> 2;
    const int t2    = (lane & 3) * 2;
    const int lr    = lane & 15;
    const int lc    = lane >> 4;
    const int bm    = blockIdx.y * 128;
    const int bn    = blockIdx.x * 128;

    const bf16* A = (MODE == 0) ? g_qbf : (MODE == 1) ? g_kvbf : g_xm;
    const bf16* W = (MODE == 0) ? g_wq  : (MODE == 1) ? g_wkv  : g_wm;

    // loader: 8 A-chunks + 8 B-chunks per thread per tile (BK=64 -> 128B rows)
    const int lrow = tid >> 3;         // 0..15 (+ it*16)
    const int lcc  = tid & 7;          // 16B chunk in row
    const bf16* srcA[8];
    const bf16* srcB[8];
    uint32_t dstOff[8];
    #pragma unroll
    for (int it = 0; it < 8; it++) {
        int row = lrow + it * 16;
        srcA[it] = A + (size_t)(bm + row) * CDIM + lcc * 8;
        srcB[it] = W + (size_t)(bn + row) * CDIM + lcc * 8;
        dstOff[it] = (uint32_t)(row * 144 + lcc * 16);
    }

    const uint32_t aoff = (uint32_t)((warpM * 64 + lr) * 144 + lc * 16);
    const uint32_t boff = (uint32_t)((warpN * 64 + lr) * 144 + lc * 16) + 18432;

    auto load_tile = [&](int t, int stage) {
        const uint32_t st = smBase + stage * GSTAGE;
        const int koff = t * 64;
        #pragma unroll
        for (int it = 0; it < 8; it++)
            cp_async16(st + dstOff[it], srcA[it] + koff);
        #pragma unroll
        for (int it = 0; it < 8; it++)
            cp_async16(st + 18432 + dstOff[it], srcB[it] + koff);
    };

    float acc[4][8][4] = {};

    load_tile(0, 0); cp_commit();
    load_tile(1, 1); cp_commit();

    #pragma unroll
    for (int t = 0; t < 8; t++) {
        cp_wait<1>();
        __syncthreads();
        if (t + 2 < 8) load_tile(t + 2, (t + 2) % 3);
        cp_commit();

        const uint32_t sa = smBase + (t % 3) * GSTAGE;
        #pragma unroll
        for (int ks = 0; ks < 4; ks++) {
            const int ko2 = ks * 32;
            unsigned af[4][4], bfm[4][4];
            #pragma unroll
            for (int ma = 0; ma < 4; ma++)
                ldm_x4(af[ma], sa + aoff + ma * 16 * 144 + ko2);
            #pragma unroll
            for (int p = 0; p < 4; p++)
                ldm_x4(bfm[p], sa + boff + p * 16 * 144 + ko2);
            #pragma unroll
            for (int ma = 0; ma < 4; ma++)
                #pragma unroll
                for (int nb = 0; nb < 8; nb++)
                    mma16816(acc[ma][nb], af[ma],
                             bfm[nb >> 1][nb & 1], bfm[nb >> 1][2 + (nb & 1)]);
        }
    }

    // bias add (warp n-span = 64)
    #pragma unroll
    for (int nb = 0; nb < 8; nb++) {
        float2 bv = *(const float2*)&bias[bn + warpN * 64 + nb * 8 + t2];
        #pragma unroll
        for (int ma = 0; ma < 4; ma++) {
            acc[ma][nb][0] += bv.x; acc[ma][nb][1] += bv.y;
            acc[ma][nb][2] += bv.x; acc[ma][nb][3] += bv.y;
        }
    }

    if (MODE == 2) {
        #pragma unroll
        for (int ma = 0; ma < 4; ma++)
            #pragma unroll
            for (int h2 = 0; h2 < 2; h2++) {
                int m = bm + warpM * 64 + ma * 16 + h2 * 8 + g;
                #pragma unroll
                for (int nb = 0; nb < 8; nb++) {
                    int n = bn + warpN * 64 + nb * 8 + t2;
                    float2 s = *(const float2*)&shortcut[(size_t)m * CDIM + n];
                    float2 o;
                    o.x = acc[ma][nb][h2 * 2 + 0] + s.x;
                    o.y = acc[ma][nb][h2 * 2 + 1] + s.y;
                    *(float2*)&out[(size_t)m * CDIM + n] = o;
                }
            }
    } else {
        // warp's 64-wide n span == one head -> quad-shuffle-only L2 norm
        const int n0 = bn + warpN * 64;
        #pragma unroll
        for (int ma = 0; ma < 4; ma++)
            #pragma unroll
            for (int h2 = 0; h2 < 2; h2++) {
                float s = 0.f;
                #pragma unroll
                for (int nb = 0; nb < 8; nb++) {
                    float x = acc[ma][nb][h2 * 2], y = acc[ma][nb][h2 * 2 + 1];
                    s += x * x + y * y;
                }
                s += __shfl_xor_sync(0xffffffffu, s, 1);
                s += __shfl_xor_sync(0xffffffffu, s, 2);
                float rn = 1.f / fmaxf(sqrtf(s), 1e-12f);
                int m = bm + warpM * 64 + ma * 16 + h2 * 8 + g;
                if (MODE == 0) {
                    int bt = m >> 8, lq = m & 255;
                    int h = n0 >> 6;
                    bf16* dst = g_qh + (((size_t)(bt * 8 + h)) * 256 + lq) * 64;
                    #pragma unroll
                    for (int nb = 0; nb < 8; nb++)
                        *(unsigned*)(dst + nb * 8 + t2) =
                            pk(acc[ma][nb][h2 * 2] * rn, acc[ma][nb][h2 * 2 + 1] * rn);
                } else {
                    int bt = m >> 9, lk = m & 511;
                    if (n0 < 512) {
                        int h = n0 >> 6;
                        bf16* dst = g_kh + (((size_t)(bt * 8 + h)) * 512 + lk) * 64;
                        #pragma unroll
                        for (int nb = 0; nb < 8; nb++)
                            *(unsigned*)(dst + nb * 8 + t2) =
                                pk(acc[ma][nb][h2 * 2] * rn, acc[ma][nb][h2 * 2 + 1] * rn);
                    } else {
                        int h = (n0 >> 6) - 8;
                        bf16* dst = g_vt + ((size_t)(bt * 8 + h)) * 64 * 512 + lk;
                        #pragma unroll
                        for (int nb = 0; nb < 8; nb++) {
                            int d = nb * 8 + t2;
                            dst[(size_t)d * 512]       = __float2bfloat16(acc[ma][nb][h2 * 2] * rn);
                            dst[(size_t)(d + 1) * 512] = __float2bfloat16(acc[ma][nb][h2 * 2 + 1] * rn);
                        }
                    }
                }
            }
    }
}

// ---------------------------------------------------------------------------
// Attention: block = (128 q-rows, h, bt), 128 threads (4 warps), warp 32q x 64k.
// 3-stage cp.async on K/V, ldmatrix fragments.
// dyn smem: Qs[128*72] | K 3x9216B | V 3x9216B = 73728 B -> 2 CTA/SM
// ---------------------------------------------------------------------------
#define ASMEM 73728

__global__ __launch_bounds__(128, 2)
void attn_bf16()
{
    extern __shared__ bf16 dsm[];
    bf16* Qs = dsm;
    const uint32_t smQ = smem_u32(dsm);
    const uint32_t smK = smQ + 18432;
    const uint32_t smV = smK + 27648;

    const int tid  = threadIdx.x;
    const int lane = tid & 31;
    const int wid  = tid >> 5;       // 0..3
    const int g    = lane >> 2;
    const int t2   = (lane & 3) * 2;
    const int lr   = lane & 15;
    const int lc   = lane >> 4;
    const int qt   = blockIdx.x;
    const int h    = blockIdx.y;
    const int bt   = blockIdx.z;

    const bf16* Qg = g_qh + (((size_t)(bt * 8 + h)) * 256 + qt * 128) * 64;
    const bf16* Kg = g_kh + ((size_t)(bt * 8 + h)) * 512 * 64;
    const bf16* Vg = g_vt + ((size_t)(bt * 8 + h)) * 64 * 512;

    auto load_kv = [&](int t) {
        const int stage = t % 3;
        const uint32_t kb = smK + stage * 9216;
        const uint32_t vb = smV + stage * 9216;
        #pragma unroll
        for (int it = 0; it < 4; it++) {
            int c   = tid + it * 128;     // 0..511
            int row = c >> 3;
            int cc  = c & 7;
            cp_async16(kb + row * 144 + cc * 16, Kg + (size_t)(t * 64 + row) * 64 + cc * 8);
            cp_async16(vb + row * 144 + cc * 16, Vg + (size_t)row * 512 + t * 64 + cc * 8);
        }
    };

    load_kv(0); cp_commit();
    load_kv(1); cp_commit();

    // Q tile 128x64 -> smem (row stride 72 bf16)
    #pragma unroll
    for (int it = 0; it < 8; it++) {
        int idx = tid + it * 128;
        int row = idx >> 3, c = (idx & 7) * 8;
        *(uint4*)&Qs[row * 72 + c] = *(const uint4*)&Qg[(size_t)row * 64 + c];
    }
    __syncthreads();

    // preload Q fragments: warp rows wid*32 .. +31
    unsigned qf[2][4][4];
    #pragma unroll
    for (int ma = 0; ma < 2; ma++) {
        const uint32_t qo = smQ + (uint32_t)((wid * 32 + ma * 16 + lr) * 144 + lc * 16);
        #pragma unroll
        for (int ka = 0; ka < 4; ka++)
            ldm_x4(qf[ma][ka], qo + ka * 32);
    }

    const uint32_t nvoff = (uint32_t)(lr * 144 + lc * 16);

    float oacc[2][8][4] = {};
    float lsum[2][2] = {};
    const float sc = 0.125f * 1.4426950408889634f;   // log2(e)/sqrt(64)

    #pragma unroll
    for (int t = 0; t < 8; t++) {
        cp_wait<1>();
        __syncthreads();
        if (t + 2 < 8) load_kv(t + 2);
        cp_commit();

        const uint32_t kb = smK + (t % 3) * 9216;
        const uint32_t vb = smV + (t % 3) * 9216;

        // S = Q K^T : warp 32q x 64k
        float sacc[2][8][4] = {};
        #pragma unroll
        for (int ka = 0; ka < 4; ka++) {
            #pragma unroll
            for (int p = 0; p < 4; p++) {
                unsigned kf[4];
                ldm_x4(kf, kb + nvoff + p * 16 * 144 + ka * 32);
                #pragma unroll
                for (int ma = 0; ma < 2; ma++) {
                    mma16816(sacc[ma][2 * p + 0], qf[ma][ka], kf[0], kf[2]);
                    mma16816(sacc[ma][2 * p + 1], qf[ma][ka], kf[1], kf[3]);
                }
            }
        }

        // exp (bounded arg), accumulate row sums
        #pragma unroll
        for (int ma = 0; ma < 2; ma++)
            #pragma unroll
            for (int nb = 0; nb < 8; nb++) {
                #pragma unroll
                for (int i = 0; i < 4; i++) {
                    float e;
                    asm("ex2.approx.f32 %0, %1;" : "=f"(e) : "f"(sacc[ma][nb][i] * sc));
                    sacc[ma][nb][i] = e;
                }
                lsum[ma][0] += sacc[ma][nb][0] + sacc[ma][nb][1];
                lsum[ma][1] += sacc[ma][nb][2] + sacc[ma][nb][3];
            }

        // O += P V
        #pragma unroll
        for (int kk = 0; kk < 4; kk++) {
            unsigned pf[2][4];
            #pragma unroll
            for (int ma = 0; ma < 2; ma++) {
                pf[ma][0] = pk(sacc[ma][2 * kk][0],     sacc[ma][2 * kk][1]);
                pf[ma][1] = pk(sacc[ma][2 * kk][2],     sacc[ma][2 * kk][3]);
                pf[ma][2] = pk(sacc[ma][2 * kk + 1][0], sacc[ma][2 * kk + 1][1]);
                pf[ma][3] = pk(sacc[ma][2 * kk + 1][2], sacc[ma][2 * kk + 1][3]);
            }
            #pragma unroll
            for (int p = 0; p < 4; p++) {
                unsigned vf[4];
                ldm_x4(vf, vb + nvoff + p * 16 * 144 + kk * 32);
                #pragma unroll
                for (int ma = 0; ma < 2; ma++) {
                    mma16816(oacc[ma][2 * p + 0], pf[ma], vf[0], vf[2]);
                    mma16816(oacc[ma][2 * p + 1], pf[ma], vf[1], vf[3]);
                }
            }
        }
    }

    bf16* Og = g_xm + ((size_t)bt * 256 + qt * 128) * 512 + h * 64;
    #pragma unroll
    for (int ma = 0; ma < 2; ma++) {
        #pragma unroll
        for (int h2 = 0; h2 < 2; h2++) {
            float s = lsum[ma][h2];
            s += __shfl_xor_sync(0xffffffffu, s, 1);
            s += __shfl_xor_sync(0xffffffffu, s, 2);
            float rl = 1.f / s;
            int r = wid * 32 + ma * 16 + h2 * 8 + g;
            #pragma unroll
            for (int nb = 0; nb < 8; nb++) {
                int n = nb * 8 + t2;
                *(unsigned*)&Og[(size_t)r * 512 + n] =
                    pk(oacc[ma][nb][h2 * 2] * rl, oacc[ma][nb][h2 * 2 + 1] * rl);
            }
        }
    }
}

// ---------------------------------------------------------------------------
extern "C" void kernel_launch(void* const* d_in, const int* in_sizes, int n_in,
                              void* d_out, int out_size)
{
    const float* q   = (const float*)d_in[0];
    const float* kv  = (const float*)d_in[1];
    const float* Wq  = (const float*)d_in[2];
    const float* bq  = (const float*)d_in[3];
    const float* Wkv = (const float*)d_in[4];
    const float* bkv = (const float*)d_in[5];
    const float* Wm  = (const float*)d_in[6];
    const float* bm  = (const float*)d_in[7];
    float* out = (float*)d_out;

    cudaFuncSetAttribute(gemm_bf16<0>, cudaFuncAttributeMaxDynamicSharedMemorySize, GSMEM);
    cudaFuncSetAttribute(gemm_bf16<1>, cudaFuncAttributeMaxDynamicSharedMemorySize, GSMEM);
    cudaFuncSetAttribute(gemm_bf16<2>, cudaFuncAttributeMaxDynamicSharedMemorySize, GSMEM);
    cudaFuncSetAttribute(attn_bf16,    cudaFuncAttributeMaxDynamicSharedMemorySize, ASMEM);

    convert_inputs <<<(Q8 + KV8) / 256, 256>>>(q, kv);
    convert_weights<<<(WQ8 + WKV8 + WM8) / 256, 256>>>(Wq, Wkv, Wm);

    gemm_bf16<0><<<dim3(4, 128), 128, GSMEM>>>(bq, nullptr, nullptr);   // 16384x512
    gemm_bf16<1><<<dim3(8, 256), 128, GSMEM>>>(bkv, nullptr, nullptr);  // 32768x1024
    attn_bf16<<<dim3(2, 8, 64), 128, ASMEM>>>();
    gemm_bf16<2><<<dim3(4, 128), 128, GSMEM>>>(bm, q, out);             // 16384x512
}

// round 9
// speedup vs baseline: 1.0932x; 1.0932x over previous
#include <cuda_runtime.h>
#include <cuda_bf16.h>
#include <math.h>
#include <stdint.h>

#define BT_N 64
#define LQ   256
#define LK   512
#define CDIM 512
#define NH   8
#define HD   64

typedef __nv_bfloat16 bf16;

// ---- device scratch ----
__device__ bf16 g_qbf [(size_t)16384 * 512];
__device__ bf16 g_kvbf[(size_t)32768 * 512];
__device__ bf16 g_wq  [512 * 512];
__device__ bf16 g_wkv [1024 * 512];
__device__ bf16 g_wm  [512 * 512];
__device__ bf16 g_qh  [(size_t)BT_N * NH * LQ * HD];
__device__ bf16 g_kh  [(size_t)BT_N * NH * LK * HD];
__device__ bf16 g_vh  [(size_t)BT_N * NH * LK * HD];   // V row-major: [bt][h][lk][d]
__device__ bf16 g_xm  [(size_t)BT_N * LQ * CDIM];

// ---------------------------------------------------------------------------
__device__ __forceinline__ unsigned pk(float lo, float hi) {
    unsigned r;
    asm("cvt.rn.bf16x2.f32 %0, %1, %2;" : "=r"(r) : "f"(hi), "f"(lo));
    return r;
}
__device__ __forceinline__ uint32_t smem_u32(const void* p) {
    uint32_t a;
    asm("{ .reg .u64 t; cvta.to.shared.u64 t, %1; cvt.u32.u64 %0, t; }" : "=r"(a) : "l"(p));
    return a;
}
__device__ __forceinline__ void cp_async16(uint32_t dst, const void* src) {
    asm volatile("cp.async.cg.shared.global [%0], [%1], 16;" :: "r"(dst), "l"(src));
}
__device__ __forceinline__ void cp_commit() { asm volatile("cp.async.commit_group;" ::: "memory"); }
template<int N> __device__ __forceinline__ void cp_wait() { asm volatile("cp.async.wait_group %0;" :: "n"(N) : "memory"); }

__device__ __forceinline__ void ldm_x4(unsigned* r, uint32_t addr) {
    asm volatile("ldmatrix.sync.aligned.m8n8.x4.shared.b16 {%0,%1,%2,%3}, [%4];"
                 : "=r"(r[0]), "=r"(r[1]), "=r"(r[2]), "=r"(r[3]) : "r"(addr));
}
__device__ __forceinline__ void ldm_x4_t(unsigned* r, uint32_t addr) {
    asm volatile("ldmatrix.sync.aligned.m8n8.x4.trans.shared.b16 {%0,%1,%2,%3}, [%4];"
                 : "=r"(r[0]), "=r"(r[1]), "=r"(r[2]), "=r"(r[3]) : "r"(addr));
}

__device__ __forceinline__ void mma16816(float* d, const unsigned* a, unsigned b0, unsigned b1) {
    asm volatile(
        "mma.sync.aligned.m16n8k16.row.col.f32.bf16.bf16.f32 "
        "{%0,%1,%2,%3},{%4,%5,%6,%7},{%8,%9},{%0,%1,%2,%3};"
        : "+f"(d[0]), "+f"(d[1]), "+f"(d[2]), "+f"(d[3])
        : "r"(a[0]), "r"(a[1]), "r"(a[2]), "r"(a[3]), "r"(b0), "r"(b1));
}

// ---------------------------------------------------------------------------
// fp32 -> bf16 conversion: single merged kernel (unit = 8 elements)
// ---------------------------------------------------------------------------
#define Q8   (16384 * 512 / 8)
#define KV8  (32768 * 512 / 8)
#define WQ8  (512 * 512 / 8)
#define WKV8 (1024 * 512 / 8)
#define WM8  (512 * 512 / 8)
#define ALL8 (Q8 + KV8 + WQ8 + WKV8 + WM8)

__device__ __forceinline__ void conv8(const float* src, bf16* dst, int i) {
    const float4 a = ((const float4*)src)[2 * i];
    const float4 b = ((const float4*)src)[2 * i + 1];
    ((uint4*)dst)[i] = make_uint4(pk(a.x, a.y), pk(a.z, a.w), pk(b.x, b.y), pk(b.z, b.w));
}

__global__ __launch_bounds__(256)
void convert_all(const float* __restrict__ q, const float* __restrict__ kv,
                 const float* __restrict__ wq, const float* __restrict__ wkv,
                 const float* __restrict__ wm) {
    int i = blockIdx.x * blockDim.x + threadIdx.x;
    if (i < Q8)                          conv8(q,   g_qbf,  i);
    else if (i < Q8 + KV8)               conv8(kv,  g_kvbf, i - Q8);
    else if (i < Q8 + KV8 + WQ8)         conv8(wq,  g_wq,   i - Q8 - KV8);
    else if (i < Q8 + KV8 + WQ8 + WKV8)  conv8(wkv, g_wkv,  i - Q8 - KV8 - WQ8);
    else                                 conv8(wm,  g_wm,   i - Q8 - KV8 - WQ8 - WKV8);
}

// ---------------------------------------------------------------------------
// bf16 GEMM (NT): CTA 128x128, BK=64, 3-stage cp.async, ldmatrix.
// 8 warps 2M x 4N, warp tile 64x32. Row stride 72 bf16 = 144 B.
// Stage = 36864 B; 3 stages = 110592 B -> 2 CTA/SM (16 warps/SM).
// ---------------------------------------------------------------------------
#define GSTAGE 36864
#define GSMEM  (3 * GSTAGE)

template<int MODE>
__global__ __launch_bounds__(256, 2)
void gemm_bf16(const float* __restrict__ bias,
               const float* __restrict__ shortcut,
               float* __restrict__ out)
{
    extern __shared__ bf16 dsm[];
    __shared__ float sred[512];
    const uint32_t smBase = smem_u32(dsm);

    const int tid   = threadIdx.x;
    const int lane  = tid & 31;
    const int wid   = tid >> 5;
    const int warpM = wid >> 2;
    const int warpN = wid & 3;
    const int g     = lane >> 2;
    const int t2    = (lane & 3) * 2;
    const int lr    = lane & 15;
    const int lc    = lane >> 4;
    const int bm    = blockIdx.y * 128;
    const int bn    = blockIdx.x * 128;

    const bf16* A = (MODE == 0) ? g_qbf : (MODE == 1) ? g_kvbf : g_xm;
    const bf16* W = (MODE == 0) ? g_wq  : (MODE == 1) ? g_wkv  : g_wm;

    const int lrow = tid >> 3;
    const int lcc  = tid & 7;
    const bf16* srcA[4];
    const bf16* srcB[4];
    uint32_t dstOff[4];
    #pragma unroll
    for (int it = 0; it < 4; it++) {
        int row = lrow + it * 32;
        srcA[it] = A + (size_t)(bm + row) * CDIM + lcc * 8;
        srcB[it] = W + (size_t)(bn + row) * CDIM + lcc * 8;
        dstOff[it] = (uint32_t)(row * 144 + lcc * 16);
    }

    const uint32_t aoff = (uint32_t)((warpM * 64 + lr) * 144 + lc * 16);
    const uint32_t boff = (uint32_t)((warpN * 32 + lr) * 144 + lc * 16) + 18432;

    auto load_tile = [&](int t, int stage) {
        const uint32_t st = smBase + stage * GSTAGE;
        const int koff = t * 64;
        #pragma unroll
        for (int it = 0; it < 4; it++)
            cp_async16(st + dstOff[it], srcA[it] + koff);
        #pragma unroll
        for (int it = 0; it < 4; it++)
            cp_async16(st + 18432 + dstOff[it], srcB[it] + koff);
    };

    float acc[4][4][4] = {};

    load_tile(0, 0); cp_commit();
    load_tile(1, 1); cp_commit();

    #pragma unroll
    for (int t = 0; t < 8; t++) {
        cp_wait<1>();
        __syncthreads();
        if (t + 2 < 8) load_tile(t + 2, (t + 2) % 3);
        cp_commit();

        const uint32_t sa = smBase + (t % 3) * GSTAGE;
        #pragma unroll
        for (int ks = 0; ks < 4; ks++) {
            const int ko2 = ks * 32;
            unsigned af[4][4], bfm[2][4];
            #pragma unroll
            for (int ma = 0; ma < 4; ma++)
                ldm_x4(af[ma], sa + aoff + ma * 16 * 144 + ko2);
            #pragma unroll
            for (int p = 0; p < 2; p++)
                ldm_x4(bfm[p], sa + boff + p * 16 * 144 + ko2);
            #pragma unroll
            for (int ma = 0; ma < 4; ma++)
                #pragma unroll
                for (int nb = 0; nb < 4; nb++)
                    mma16816(acc[ma][nb], af[ma],
                             bfm[nb >> 1][nb & 1], bfm[nb >> 1][2 + (nb & 1)]);
        }
    }

    // bias add
    float2 bv[4];
    #pragma unroll
    for (int nb = 0; nb < 4; nb++)
        bv[nb] = *(const float2*)&bias[bn + warpN * 32 + nb * 8 + t2];
    #pragma unroll
    for (int ma = 0; ma < 4; ma++)
        #pragma unroll
        for (int nb = 0; nb < 4; nb++) {
            acc[ma][nb][0] += bv[nb].x; acc[ma][nb][1] += bv[nb].y;
            acc[ma][nb][2] += bv[nb].x; acc[ma][nb][3] += bv[nb].y;
        }

    if (MODE == 2) {
        #pragma unroll
        for (int ma = 0; ma < 4; ma++)
            #pragma unroll
            for (int h2 = 0; h2 < 2; h2++) {
                int m = bm + warpM * 64 + ma * 16 + h2 * 8 + g;
                #pragma unroll
                for (int nb = 0; nb < 4; nb++) {
                    int n = bn + warpN * 32 + nb * 8 + t2;
                    float2 s = *(const float2*)&shortcut[(size_t)m * CDIM + n];
                    float2 o;
                    o.x = acc[ma][nb][h2 * 2 + 0] + s.x;
                    o.y = acc[ma][nb][h2 * 2 + 1] + s.y;
                    *(float2*)&out[(size_t)m * CDIM + n] = o;
                }
            }
    } else {
        float ssq[4][2];
        #pragma unroll
        for (int ma = 0; ma < 4; ma++)
            #pragma unroll
            for (int h2 = 0; h2 < 2; h2++) {
                float s = 0.f;
                #pragma unroll
                for (int nb = 0; nb < 4; nb++) {
                    float x = acc[ma][nb][h2 * 2], y = acc[ma][nb][h2 * 2 + 1];
                    s += x * x + y * y;
                }
                s += __shfl_xor_sync(0xffffffffu, s, 1);
                s += __shfl_xor_sync(0xffffffffu, s, 2);
                ssq[ma][h2] = s;
            }
        __syncthreads();
        if ((lane & 3) == 0) {
            #pragma unroll
            for (int ma = 0; ma < 4; ma++)
                #pragma unroll
                for (int h2 = 0; h2 < 2; h2++)
                    sred[wid * 64 + ma * 16 + h2 * 8 + g] = ssq[ma][h2];
        }
        __syncthreads();
        #pragma unroll
        for (int ma = 0; ma < 4; ma++)
            #pragma unroll
            for (int h2 = 0; h2 < 2; h2++) {
                int r = ma * 16 + h2 * 8 + g;
                float tot = sred[(wid & ~1) * 64 + r] + sred[((wid & ~1) + 1) * 64 + r];
                float rn = 1.f / fmaxf(sqrtf(tot), 1e-12f);
                int m = bm + warpM * 64 + r;
                #pragma unroll
                for (int nb = 0; nb < 4; nb++) {
                    int n = bn + warpN * 32 + nb * 8 + t2;
                    float v0 = acc[ma][nb][h2 * 2] * rn;
                    float v1 = acc[ma][nb][h2 * 2 + 1] * rn;
                    if (MODE == 0) {
                        int bt = m >> 8, lq = m & 255;
                        int h = n >> 6, d = n & 63;
                        *(unsigned*)&g_qh[(((size_t)(bt * 8 + h)) * 256 + lq) * 64 + d] = pk(v0, v1);
                    } else {
                        int bt = m >> 9, lk = m & 511;
                        int h = (n >> 6) & 7, d = n & 63;
                        bf16* base = (n < 512) ? g_kh : g_vh;   // V now row-major, coalesced
                        *(unsigned*)&base[(((size_t)(bt * 8 + h)) * 512 + lk) * 64 + d] = pk(v0, v1);
                    }
                }
            }
    }
}

// ---------------------------------------------------------------------------
// Attention: block = (128 q-rows, h, bt), 8 warps, warp 16q x 64k.
// 3-stage cp.async on K/V (both row-major [lk][d]); V fragments via
// ldmatrix.trans (LDSM_T). dyn smem 73728 B -> 2 CTA/SM.
// ---------------------------------------------------------------------------
#define ASMEM 73728

__global__ __launch_bounds__(256)
void attn_bf16()
{
    extern __shared__ bf16 dsm[];
    bf16* Qs = dsm;
    const uint32_t smQ = smem_u32(dsm);
    const uint32_t smK = smQ + 9216 * 2;
    const uint32_t smV = smK + 13824 * 2;

    const int tid  = threadIdx.x;
    const int lane = tid & 31;
    const int wid  = tid >> 5;
    const int g    = lane >> 2;
    const int t2   = (lane & 3) * 2;
    const int lr   = lane & 15;
    const int lc   = lane >> 4;
    const int qt   = blockIdx.x;
    const int h    = blockIdx.y;
    const int bt   = blockIdx.z;

    const bf16* Qg = g_qh + (((size_t)(bt * 8 + h)) * 256 + qt * 128) * 64;
    const bf16* Kg = g_kh + ((size_t)(bt * 8 + h)) * 512 * 64;
    const bf16* Vg = g_vh + ((size_t)(bt * 8 + h)) * 512 * 64;

    auto load_kv = [&](int t) {
        const int stage = t % 3;
        const uint32_t kb = smK + stage * 4608 * 2;
        const uint32_t vb = smV + stage * 4608 * 2;
        #pragma unroll
        for (int it = 0; it < 2; it++) {
            int c   = tid + it * 256;
            int row = c >> 3;
            int cc  = c & 7;
            cp_async16(kb + row * 144 + cc * 16, Kg + (size_t)(t * 64 + row) * 64 + cc * 8);
            cp_async16(vb + row * 144 + cc * 16, Vg + (size_t)(t * 64 + row) * 64 + cc * 8);
        }
    };

    load_kv(0); cp_commit();
    load_kv(1); cp_commit();

    #pragma unroll
    for (int it = 0; it < 4; it++) {
        int idx = tid + it * 256;
        int row = idx >> 3, c = (idx & 7) * 8;
        *(uint4*)&Qs[row * 72 + c] = *(const uint4*)&Qg[(size_t)row * 64 + c];
    }
    __syncthreads();

    unsigned qf[4][4];
    {
        const uint32_t qoff = smQ + (uint32_t)((wid * 16 + lr) * 144 + lc * 16);
        #pragma unroll
        for (int ka = 0; ka < 4; ka++)
            ldm_x4(qf[ka], qoff + ka * 32);
    }

    const uint32_t nvoff = (uint32_t)(lr * 144 + lc * 16);

    float oacc[8][4] = {};
    float lsum0 = 0.f, lsum1 = 0.f;
    const float sc = 0.125f * 1.4426950408889634f;

    #pragma unroll
    for (int t = 0; t < 8; t++) {
        cp_wait<1>();
        __syncthreads();
        if (t + 2 < 8) load_kv(t + 2);
        cp_commit();

        const uint32_t kb = smK + (t % 3) * 4608 * 2;
        const uint32_t vb = smV + (t % 3) * 4608 * 2;

        // S = Q K^T (K row-major, non-trans ldmatrix)
        float sacc[8][4] = {};
        #pragma unroll
        for (int ka = 0; ka < 4; ka++) {
            #pragma unroll
            for (int p = 0; p < 4; p++) {
                unsigned kf[4];
                ldm_x4(kf, kb + nvoff + p * 16 * 144 + ka * 32);
                mma16816(sacc[2 * p + 0], qf[ka], kf[0], kf[2]);
                mma16816(sacc[2 * p + 1], qf[ka], kf[1], kf[3]);
            }
        }

        #pragma unroll
        for (int nb = 0; nb < 8; nb++) {
            #pragma unroll
            for (int i = 0; i < 4; i++) {
                float e;
                asm("ex2.approx.f32 %0, %1;" : "=f"(e) : "f"(sacc[nb][i] * sc));
                sacc[nb][i] = e;
            }
            lsum0 += sacc[nb][0] + sacc[nb][1];
            lsum1 += sacc[nb][2] + sacc[nb][3];
        }

        // O += P V  (V row-major; B fragments via ldmatrix.trans on k-rows)
        #pragma unroll
        for (int kk = 0; kk < 4; kk++) {
            unsigned pf[4];
            pf[0] = pk(sacc[2 * kk][0],     sacc[2 * kk][1]);
            pf[1] = pk(sacc[2 * kk][2],     sacc[2 * kk][3]);
            pf[2] = pk(sacc[2 * kk + 1][0], sacc[2 * kk + 1][1]);
            pf[3] = pk(sacc[2 * kk + 1][2], sacc[2 * kk + 1][3]);
            #pragma unroll
            for (int p = 0; p < 4; p++) {
                unsigned vf[4];
                ldm_x4_t(vf, vb + (kk * 16 + lr) * 144 + lc * 16 + p * 32);
                mma16816(oacc[2 * p + 0], pf, vf[0], vf[1]);
                mma16816(oacc[2 * p + 1], pf, vf[2], vf[3]);
            }
        }
    }

    lsum0 += __shfl_xor_sync(0xffffffffu, lsum0, 1);
    lsum0 += __shfl_xor_sync(0xffffffffu, lsum0, 2);
    lsum1 += __shfl_xor_sync(0xffffffffu, lsum1, 1);
    lsum1 += __shfl_xor_sync(0xffffffffu, lsum1, 2);
    const float rl0 = 1.f / lsum0, rl1 = 1.f / lsum1;

    bf16* Og = g_xm + ((size_t)bt * 256 + qt * 128) * 512 + h * 64;
    const int r0 = wid * 16 + g;
    #pragma unroll
    for (int nb = 0; nb < 8; nb++) {
        int n = nb * 8 + t2;
        *(unsigned*)&Og[(size_t)r0 * 512 + n]       = pk(oacc[nb][0] * rl0, oacc[nb][1] * rl0);
        *(unsigned*)&Og[(size_t)(r0 + 8) * 512 + n] = pk(oacc[nb][2] * rl1, oacc[nb][3] * rl1);
    }
}

// ---------------------------------------------------------------------------
extern "C" void kernel_launch(void* const* d_in, const int* in_sizes, int n_in,
                              void* d_out, int out_size)
{
    const float* q   = (const float*)d_in[0];
    const float* kv  = (const float*)d_in[1];
    const float* Wq  = (const float*)d_in[2];
    const float* bq  = (const float*)d_in[3];
    const float* Wkv = (const float*)d_in[4];
    const float* bkv = (const float*)d_in[5];
    const float* Wm  = (const float*)d_in[6];
    const float* bm  = (const float*)d_in[7];
    float* out = (float*)d_out;

    cudaFuncSetAttribute(gemm_bf16<0>, cudaFuncAttributeMaxDynamicSharedMemorySize, GSMEM);
    cudaFuncSetAttribute(gemm_bf16<1>, cudaFuncAttributeMaxDynamicSharedMemorySize, GSMEM);
    cudaFuncSetAttribute(gemm_bf16<2>, cudaFuncAttributeMaxDynamicSharedMemorySize, GSMEM);
    cudaFuncSetAttribute(attn_bf16,    cudaFuncAttributeMaxDynamicSharedMemorySize, ASMEM);

    convert_all<<<ALL8 / 256, 256>>>(q, kv, Wq, Wkv, Wm);

    gemm_bf16<0><<<dim3(4, 128), 256, GSMEM>>>(bq, nullptr, nullptr);   // 16384x512
    gemm_bf16<1><<<dim3(8, 256), 256, GSMEM>>>(bkv, nullptr, nullptr);  // 32768x1024
    attn_bf16<<<dim3(2, 8, 64), 256, ASMEM>>>();
    gemm_bf16<2><<<dim3(4, 128), 256, GSMEM>>>(bm, q, out);             // 16384x512
}

// round 10
// speedup vs baseline: 1.1231x; 1.0274x over previous
#include <cuda_runtime.h>
#include <cuda_bf16.h>
#include <math.h>
#include <stdint.h>

#define BT_N 64
#define LQ   256
#define LK   512
#define CDIM 512
#define NH   8
#define HD   64

typedef __nv_bfloat16 bf16;

// ---- device scratch ----
__device__ bf16 g_qbf [(size_t)16384 * 512];
__device__ bf16 g_kvbf[(size_t)32768 * 512];
__device__ bf16 g_wq  [512 * 512];
__device__ bf16 g_wkv [1024 * 512];
__device__ bf16 g_wm  [512 * 512];
__device__ bf16 g_qh  [(size_t)BT_N * NH * LQ * HD];
__device__ bf16 g_kh  [(size_t)BT_N * NH * LK * HD];
__device__ bf16 g_vh  [(size_t)BT_N * NH * LK * HD];   // V row-major: [bt][h][lk][d]
__device__ bf16 g_xm  [(size_t)BT_N * LQ * CDIM];

// ---------------------------------------------------------------------------
__device__ __forceinline__ unsigned pk(float lo, float hi) {
    unsigned r;
    asm("cvt.rn.bf16x2.f32 %0, %1, %2;" : "=r"(r) : "f"(hi), "f"(lo));
    return r;
}
__device__ __forceinline__ uint32_t smem_u32(const void* p) {
    uint32_t a;
    asm("{ .reg .u64 t; cvta.to.shared.u64 t, %1; cvt.u32.u64 %0, t; }" : "=r"(a) : "l"(p));
    return a;
}
__device__ __forceinline__ void cp_async16(uint32_t dst, const void* src) {
    asm volatile("cp.async.cg.shared.global [%0], [%1], 16;" :: "r"(dst), "l"(src));
}
__device__ __forceinline__ void cp_commit() { asm volatile("cp.async.commit_group;" ::: "memory"); }
template<int N> __device__ __forceinline__ void cp_wait() { asm volatile("cp.async.wait_group %0;" :: "n"(N) : "memory"); }

__device__ __forceinline__ void ldm_x4(unsigned* r, uint32_t addr) {
    asm volatile("ldmatrix.sync.aligned.m8n8.x4.shared.b16 {%0,%1,%2,%3}, [%4];"
                 : "=r"(r[0]), "=r"(r[1]), "=r"(r[2]), "=r"(r[3]) : "r"(addr));
}
__device__ __forceinline__ void ldm_x4_t(unsigned* r, uint32_t addr) {
    asm volatile("ldmatrix.sync.aligned.m8n8.x4.trans.shared.b16 {%0,%1,%2,%3}, [%4];"
                 : "=r"(r[0]), "=r"(r[1]), "=r"(r[2]), "=r"(r[3]) : "r"(addr));
}

__device__ __forceinline__ void mma16816(float* d, const unsigned* a, unsigned b0, unsigned b1) {
    asm volatile(
        "mma.sync.aligned.m16n8k16.row.col.f32.bf16.bf16.f32 "
        "{%0,%1,%2,%3},{%4,%5,%6,%7},{%8,%9},{%0,%1,%2,%3};"
        : "+f"(d[0]), "+f"(d[1]), "+f"(d[2]), "+f"(d[3])
        : "r"(a[0]), "r"(a[1]), "r"(a[2]), "r"(a[3]), "r"(b0), "r"(b1));
}

// ---------------------------------------------------------------------------
// fp32 -> bf16 conversion: single merged kernel (unit = 8 elements)
// ---------------------------------------------------------------------------
#define Q8   (16384 * 512 / 8)
#define KV8  (32768 * 512 / 8)
#define WQ8  (512 * 512 / 8)
#define WKV8 (1024 * 512 / 8)
#define WM8  (512 * 512 / 8)
#define ALL8 (Q8 + KV8 + WQ8 + WKV8 + WM8)

__device__ __forceinline__ void conv8(const float* src, bf16* dst, int i) {
    const float4 a = ((const float4*)src)[2 * i];
    const float4 b = ((const float4*)src)[2 * i + 1];
    ((uint4*)dst)[i] = make_uint4(pk(a.x, a.y), pk(a.z, a.w), pk(b.x, b.y), pk(b.z, b.w));
}

__global__ __launch_bounds__(256)
void convert_all(const float* __restrict__ q, const float* __restrict__ kv,
                 const float* __restrict__ wq, const float* __restrict__ wkv,
                 const float* __restrict__ wm) {
    int i = blockIdx.x * blockDim.x + threadIdx.x;
    if (i < Q8)                          conv8(q,   g_qbf,  i);
    else if (i < Q8 + KV8)               conv8(kv,  g_kvbf, i - Q8);
    else if (i < Q8 + KV8 + WQ8)         conv8(wq,  g_wq,   i - Q8 - KV8);
    else if (i < Q8 + KV8 + WQ8 + WKV8)  conv8(wkv, g_wkv,  i - Q8 - KV8 - WQ8);
    else                                 conv8(wm,  g_wm,   i - Q8 - KV8 - WQ8 - WKV8);
}

// ---------------------------------------------------------------------------
// bf16 GEMM (NT): CTA 128x128, BK=64, 3-stage cp.async, ldmatrix.
// 8 warps 2M x 4N, warp tile 64x32. Row stride 72 bf16 = 144 B.
// Stage = 36864 B; 3 stages = 110592 B -> 2 CTA/SM (16 warps/SM).
// ---------------------------------------------------------------------------
#define GSTAGE 36864
#define GSMEM  (3 * GSTAGE)

template<int MODE>
__global__ __launch_bounds__(256, 2)
void gemm_bf16(const float* __restrict__ bias,
               const float* __restrict__ shortcut,
               float* __restrict__ out)
{
    extern __shared__ bf16 dsm[];
    __shared__ float sred[512];
    const uint32_t smBase = smem_u32(dsm);

    const int tid   = threadIdx.x;
    const int lane  = tid & 31;
    const int wid   = tid >> 5;
    const int warpM = wid >> 2;
    const int warpN = wid & 3;
    const int g     = lane >> 2;
    const int t2    = (lane & 3) * 2;
    const int lr    = lane & 15;
    const int lc    = lane >> 4;
    const int bm    = blockIdx.y * 128;
    const int bn    = blockIdx.x * 128;

    const bf16* A = (MODE == 0) ? g_qbf : (MODE == 1) ? g_kvbf : g_xm;
    const bf16* W = (MODE == 0) ? g_wq  : (MODE == 1) ? g_wkv  : g_wm;

    const int lrow = tid >> 3;
    const int lcc  = tid & 7;
    const bf16* srcA[4];
    const bf16* srcB[4];
    uint32_t dstOff[4];
    #pragma unroll
    for (int it = 0; it < 4; it++) {
        int row = lrow + it * 32;
        srcA[it] = A + (size_t)(bm + row) * CDIM + lcc * 8;
        srcB[it] = W + (size_t)(bn + row) * CDIM + lcc * 8;
        dstOff[it] = (uint32_t)(row * 144 + lcc * 16);
    }

    const uint32_t aoff = (uint32_t)((warpM * 64 + lr) * 144 + lc * 16);
    const uint32_t boff = (uint32_t)((warpN * 32 + lr) * 144 + lc * 16) + 18432;

    auto load_tile = [&](int t, int stage) {
        const uint32_t st = smBase + stage * GSTAGE;
        const int koff = t * 64;
        #pragma unroll
        for (int it = 0; it < 4; it++)
            cp_async16(st + dstOff[it], srcA[it] + koff);
        #pragma unroll
        for (int it = 0; it < 4; it++)
            cp_async16(st + 18432 + dstOff[it], srcB[it] + koff);
    };

    float acc[4][4][4] = {};

    load_tile(0, 0); cp_commit();
    load_tile(1, 1); cp_commit();

    #pragma unroll
    for (int t = 0; t < 8; t++) {
        cp_wait<1>();
        __syncthreads();
        if (t + 2 < 8) load_tile(t + 2, (t + 2) % 3);
        cp_commit();

        const uint32_t sa = smBase + (t % 3) * GSTAGE;
        #pragma unroll
        for (int ks = 0; ks < 4; ks++) {
            const int ko2 = ks * 32;
            unsigned af[4][4], bfm[2][4];
            #pragma unroll
            for (int ma = 0; ma < 4; ma++)
                ldm_x4(af[ma], sa + aoff + ma * 16 * 144 + ko2);
            #pragma unroll
            for (int p = 0; p < 2; p++)
                ldm_x4(bfm[p], sa + boff + p * 16 * 144 + ko2);
            #pragma unroll
            for (int ma = 0; ma < 4; ma++)
                #pragma unroll
                for (int nb = 0; nb < 4; nb++)
                    mma16816(acc[ma][nb], af[ma],
                             bfm[nb >> 1][nb & 1], bfm[nb >> 1][2 + (nb & 1)]);
        }
    }

    // bias add
    float2 bv[4];
    #pragma unroll
    for (int nb = 0; nb < 4; nb++)
        bv[nb] = *(const float2*)&bias[bn + warpN * 32 + nb * 8 + t2];
    #pragma unroll
    for (int ma = 0; ma < 4; ma++)
        #pragma unroll
        for (int nb = 0; nb < 4; nb++) {
            acc[ma][nb][0] += bv[nb].x; acc[ma][nb][1] += bv[nb].y;
            acc[ma][nb][2] += bv[nb].x; acc[ma][nb][3] += bv[nb].y;
        }

    if (MODE == 2) {
        #pragma unroll
        for (int ma = 0; ma < 4; ma++)
            #pragma unroll
            for (int h2 = 0; h2 < 2; h2++) {
                int m = bm + warpM * 64 + ma * 16 + h2 * 8 + g;
                #pragma unroll
                for (int nb = 0; nb < 4; nb++) {
                    int n = bn + warpN * 32 + nb * 8 + t2;
                    float2 s = *(const float2*)&shortcut[(size_t)m * CDIM + n];
                    float2 o;
                    o.x = acc[ma][nb][h2 * 2 + 0] + s.x;
                    o.y = acc[ma][nb][h2 * 2 + 1] + s.y;
                    *(float2*)&out[(size_t)m * CDIM + n] = o;
                }
            }
    } else {
        float ssq[4][2];
        #pragma unroll
        for (int ma = 0; ma < 4; ma++)
            #pragma unroll
            for (int h2 = 0; h2 < 2; h2++) {
                float s = 0.f;
                #pragma unroll
                for (int nb = 0; nb < 4; nb++) {
                    float x = acc[ma][nb][h2 * 2], y = acc[ma][nb][h2 * 2 + 1];
                    s += x * x + y * y;
                }
                s += __shfl_xor_sync(0xffffffffu, s, 1);
                s += __shfl_xor_sync(0xffffffffu, s, 2);
                ssq[ma][h2] = s;
            }
        __syncthreads();
        if ((lane & 3) == 0) {
            #pragma unroll
            for (int ma = 0; ma < 4; ma++)
                #pragma unroll
                for (int h2 = 0; h2 < 2; h2++)
                    sred[wid * 64 + ma * 16 + h2 * 8 + g] = ssq[ma][h2];
        }
        __syncthreads();
        #pragma unroll
        for (int ma = 0; ma < 4; ma++)
            #pragma unroll
            for (int h2 = 0; h2 < 2; h2++) {
                int r = ma * 16 + h2 * 8 + g;
                float tot = sred[(wid & ~1) * 64 + r] + sred[((wid & ~1) + 1) * 64 + r];
                float rn = 1.f / fmaxf(sqrtf(tot), 1e-12f);
                int m = bm + warpM * 64 + r;
                #pragma unroll
                for (int nb = 0; nb < 4; nb++) {
                    int n = bn + warpN * 32 + nb * 8 + t2;
                    float v0 = acc[ma][nb][h2 * 2] * rn;
                    float v1 = acc[ma][nb][h2 * 2 + 1] * rn;
                    if (MODE == 0) {
                        int bt = m >> 8, lq = m & 255;
                        int h = n >> 6, d = n & 63;
                        *(unsigned*)&g_qh[(((size_t)(bt * 8 + h)) * 256 + lq) * 64 + d] = pk(v0, v1);
                    } else {
                        int bt = m >> 9, lk = m & 511;
                        int h = (n >> 6) & 7, d = n & 63;
                        bf16* base = (n < 512) ? g_kh : g_vh;
                        *(unsigned*)&base[(((size_t)(bt * 8 + h)) * 512 + lk) * 64 + d] = pk(v0, v1);
                    }
                }
            }
    }
}

// ---------------------------------------------------------------------------
// Attention: block = (128 q-rows, h, bt), 8 warps, warp 16q x 64k.
// Per-16-key streaming: compute S-block, exp, PV immediately (8 live sacc).
// __launch_bounds__(256,2) -> <=128 regs -> 2 CTA/SM (16 warps).
// dyn smem 73728 B.
// ---------------------------------------------------------------------------
#define ASMEM 73728

__global__ __launch_bounds__(256, 2)
void attn_bf16()
{
    extern __shared__ bf16 dsm[];
    bf16* Qs = dsm;
    const uint32_t smQ = smem_u32(dsm);
    const uint32_t smK = smQ + 9216 * 2;
    const uint32_t smV = smK + 13824 * 2;

    const int tid  = threadIdx.x;
    const int lane = tid & 31;
    const int wid  = tid >> 5;
    const int g    = lane >> 2;
    const int t2   = (lane & 3) * 2;
    const int lr   = lane & 15;
    const int lc   = lane >> 4;
    const int qt   = blockIdx.x;
    const int h    = blockIdx.y;
    const int bt   = blockIdx.z;

    const bf16* Qg = g_qh + (((size_t)(bt * 8 + h)) * 256 + qt * 128) * 64;
    const bf16* Kg = g_kh + ((size_t)(bt * 8 + h)) * 512 * 64;
    const bf16* Vg = g_vh + ((size_t)(bt * 8 + h)) * 512 * 64;

    auto load_kv = [&](int t) {
        const int stage = t % 3;
        const uint32_t kb = smK + stage * 4608 * 2;
        const uint32_t vb = smV + stage * 4608 * 2;
        #pragma unroll
        for (int it = 0; it < 2; it++) {
            int c   = tid + it * 256;
            int row = c >> 3;
            int cc  = c & 7;
            cp_async16(kb + row * 144 + cc * 16, Kg + (size_t)(t * 64 + row) * 64 + cc * 8);
            cp_async16(vb + row * 144 + cc * 16, Vg + (size_t)(t * 64 + row) * 64 + cc * 8);
        }
    };

    load_kv(0); cp_commit();
    load_kv(1); cp_commit();

    #pragma unroll
    for (int it = 0; it < 4; it++) {
        int idx = tid + it * 256;
        int row = idx >> 3, c = (idx & 7) * 8;
        *(uint4*)&Qs[row * 72 + c] = *(const uint4*)&Qg[(size_t)row * 64 + c];
    }
    __syncthreads();

    unsigned qf[4][4];
    {
        const uint32_t qoff = smQ + (uint32_t)((wid * 16 + lr) * 144 + lc * 16);
        #pragma unroll
        for (int ka = 0; ka < 4; ka++)
            ldm_x4(qf[ka], qoff + ka * 32);
    }

    const uint32_t nvoff = (uint32_t)(lr * 144 + lc * 16);

    float oacc[8][4] = {};
    float lsum0 = 0.f, lsum1 = 0.f;
    const float sc = 0.125f * 1.4426950408889634f;

    #pragma unroll
    for (int t = 0; t < 8; t++) {
        cp_wait<1>();
        __syncthreads();
        if (t + 2 < 8) load_kv(t + 2);
        cp_commit();

        const uint32_t kb = smK + (t % 3) * 4608 * 2;
        const uint32_t vb = smV + (t % 3) * 4608 * 2;

        // stream 16 keys at a time: S-block -> exp -> PV
        #pragma unroll
        for (int p = 0; p < 4; p++) {
            float s0[4] = {}, s1[4] = {};
            #pragma unroll
            for (int ka = 0; ka < 4; ka++) {
                unsigned kf[4];
                ldm_x4(kf, kb + nvoff + p * 16 * 144 + ka * 32);
                mma16816(s0, qf[ka], kf[0], kf[2]);
                mma16816(s1, qf[ka], kf[1], kf[3]);
            }
            #pragma unroll
            for (int i = 0; i < 4; i++) {
                float e0, e1;
                asm("ex2.approx.f32 %0, %1;" : "=f"(e0) : "f"(s0[i] * sc));
                asm("ex2.approx.f32 %0, %1;" : "=f"(e1) : "f"(s1[i] * sc));
                s0[i] = e0; s1[i] = e1;
            }
            lsum0 += s0[0] + s0[1] + s1[0] + s1[1];
            lsum1 += s0[2] + s0[3] + s1[2] + s1[3];

            unsigned pf[4];
            pf[0] = pk(s0[0], s0[1]);
            pf[1] = pk(s0[2], s0[3]);
            pf[2] = pk(s1[0], s1[1]);
            pf[3] = pk(s1[2], s1[3]);

            #pragma unroll
            for (int d = 0; d < 4; d++) {
                unsigned vf[4];
                ldm_x4_t(vf, vb + (p * 16 + lr) * 144 + lc * 16 + d * 32);
                mma16816(oacc[2 * d + 0], pf, vf[0], vf[1]);
                mma16816(oacc[2 * d + 1], pf, vf[2], vf[3]);
            }
        }
    }

    lsum0 += __shfl_xor_sync(0xffffffffu, lsum0, 1);
    lsum0 += __shfl_xor_sync(0xffffffffu, lsum0, 2);
    lsum1 += __shfl_xor_sync(0xffffffffu, lsum1, 1);
    lsum1 += __shfl_xor_sync(0xffffffffu, lsum1, 2);
    const float rl0 = 1.f / lsum0, rl1 = 1.f / lsum1;

    bf16* Og = g_xm + ((size_t)bt * 256 + qt * 128) * 512 + h * 64;
    const int r0 = wid * 16 + g;
    #pragma unroll
    for (int nb = 0; nb < 8; nb++) {
        int n = nb * 8 + t2;
        *(unsigned*)&Og[(size_t)r0 * 512 + n]       = pk(oacc[nb][0] * rl0, oacc[nb][1] * rl0);
        *(unsigned*)&Og[(size_t)(r0 + 8) * 512 + n] = pk(oacc[nb][2] * rl1, oacc[nb][3] * rl1);
    }
}

// ---------------------------------------------------------------------------
extern "C" void kernel_launch(void* const* d_in, const int* in_sizes, int n_in,
                              void* d_out, int out_size)
{
    const float* q   = (const float*)d_in[0];
    const float* kv  = (const float*)d_in[1];
    const float* Wq  = (const float*)d_in[2];
    const float* bq  = (const float*)d_in[3];
    const float* Wkv = (const float*)d_in[4];
    const float* bkv = (const float*)d_in[5];
    const float* Wm  = (const float*)d_in[6];
    const float* bm  = (const float*)d_in[7];
    float* out = (float*)d_out;

    cudaFuncSetAttribute(gemm_bf16<0>, cudaFuncAttributeMaxDynamicSharedMemorySize, GSMEM);
    cudaFuncSetAttribute(gemm_bf16<1>, cudaFuncAttributeMaxDynamicSharedMemorySize, GSMEM);
    cudaFuncSetAttribute(gemm_bf16<2>, cudaFuncAttributeMaxDynamicSharedMemorySize, GSMEM);
    cudaFuncSetAttribute(attn_bf16,    cudaFuncAttributeMaxDynamicSharedMemorySize, ASMEM);

    convert_all<<<ALL8 / 256, 256>>>(q, kv, Wq, Wkv, Wm);

    gemm_bf16<0><<<dim3(4, 128), 256, GSMEM>>>(bq, nullptr, nullptr);   // 16384x512
    gemm_bf16<1><<<dim3(8, 256), 256, GSMEM>>>(bkv, nullptr, nullptr);  // 32768x1024
    attn_bf16<<<dim3(2, 8, 64), 256, ASMEM>>>();
    gemm_bf16<2><<<dim3(4, 128), 256, GSMEM>>>(bm, q, out);             // 16384x512
}